// round 4
// baseline (speedup 1.0000x reference)
#include <cuda_runtime.h>
#include <cstdint>

// CenterLoss: loss = (1/B) * sum_b clamp(|x_b|^2 + |c_l|^2 - 2 x_b·c_l, 1e-12, 1e12)
//                    + (C-1)*1e-12
// One-hot mask on the full [B,C] distmat keeps only the true-label column;
// each masked-out zero clamps to 1e-12 (constant (C-1)*1e-12 per row avg).
//
// B=16384, C=1000, D=512. One warp per row, single fused kernel:
// last-block-done pattern performs the finalize (no second launch).

#define B_ROWS 16384
#define C_CLASSES 1000
#define D_DIM 512
#define WARPS_PER_BLOCK 8
#define THREADS (WARPS_PER_BLOCK * 32)
#define GRID_BLOCKS (B_ROWS / WARPS_PER_BLOCK)   // 2048

__device__ double g_accum = 0.0;
__device__ unsigned int g_done = 0;

__global__ __launch_bounds__(THREADS) void center_loss_fused(
    const float* __restrict__ x,
    const int* __restrict__ labels,
    const float* __restrict__ centers,
    float* __restrict__ out)
{
    __shared__ double block_sum;
    const int warp_in_block = threadIdx.x >> 5;
    const int lane = threadIdx.x & 31;
    const int row = blockIdx.x * WARPS_PER_BLOCK + warp_in_block;

    if (threadIdx.x == 0) block_sum = 0.0;
    __syncthreads();

    {
        int lbl = labels[row];
        // defensive clamp: never index outside centers
        lbl = (lbl < 0) ? 0 : ((lbl >= C_CLASSES) ? C_CLASSES - 1 : lbl);

        const float4* __restrict__ xr =
            reinterpret_cast<const float4*>(x + (size_t)row * D_DIM);
        const float4* __restrict__ cr =
            reinterpret_cast<const float4*>(centers + (size_t)lbl * D_DIM);

        // 512 floats / 32 lanes = 16 floats = 4 float4 per lane; loads
        // front-batched for MLP.
        float4 xv[4], cv[4];
#pragma unroll
        for (int i = 0; i < 4; i++) xv[i] = xr[lane + 32 * i];
#pragma unroll
        for (int i = 0; i < 4; i++) cv[i] = cr[lane + 32 * i];

        float xs = 0.f, cs = 0.f, xc = 0.f;
#pragma unroll
        for (int i = 0; i < 4; i++) {
            xs = fmaf(xv[i].x, xv[i].x, xs);
            xs = fmaf(xv[i].y, xv[i].y, xs);
            xs = fmaf(xv[i].z, xv[i].z, xs);
            xs = fmaf(xv[i].w, xv[i].w, xs);
            cs = fmaf(cv[i].x, cv[i].x, cs);
            cs = fmaf(cv[i].y, cv[i].y, cs);
            cs = fmaf(cv[i].z, cv[i].z, cs);
            cs = fmaf(cv[i].w, cv[i].w, cs);
            xc = fmaf(xv[i].x, cv[i].x, xc);
            xc = fmaf(xv[i].y, cv[i].y, xc);
            xc = fmaf(xv[i].z, cv[i].z, xc);
            xc = fmaf(xv[i].w, cv[i].w, xc);
        }

        // warp reduction
#pragma unroll
        for (int o = 16; o > 0; o >>= 1) {
            xs += __shfl_xor_sync(0xFFFFFFFFu, xs, o);
            cs += __shfl_xor_sync(0xFFFFFFFFu, cs, o);
            xc += __shfl_xor_sync(0xFFFFFFFFu, xc, o);
        }

        if (lane == 0) {
            float d = xs + cs - 2.0f * xc;     // same formula as reference
            d = fminf(fmaxf(d, 1e-12f), 1e12f);
            atomicAdd(&block_sum, (double)d);
        }
    }
    __syncthreads();

    if (threadIdx.x == 0) {
        atomicAdd(&g_accum, block_sum);
        __threadfence();
        unsigned int prev = atomicAdd(&g_done, 1u);
        if (prev == GRID_BLOCKS - 1) {
            // last block: all g_accum adds are visible (fence + atomic order)
            double loss = g_accum / (double)B_ROWS
                        + (double)(C_CLASSES - 1) * 1e-12;
            out[0] = (float)loss;
            // reset for next graph replay
            g_accum = 0.0;
            g_done = 0u;
            __threadfence();
        }
    }
}

extern "C" void kernel_launch(void* const* d_in, const int* in_sizes, int n_in,
                              void* d_out, int out_size)
{
    const float* x = (const float*)d_in[0];
    const int* labels = (const int*)d_in[1];
    const float* centers = (const float*)d_in[2];
    float* out = (float*)d_out;

    center_loss_fused<<<GRID_BLOCKS, THREADS>>>(x, labels, centers, out);
}

// round 5
// speedup vs baseline: 1.0133x; 1.0133x over previous
#include <cuda_runtime.h>
#include <cstdint>

// CenterLoss: loss = (1/B) * sum_b clamp(|x_b|^2 + |c_l|^2 - 2 x_b·c_l, 1e-12, 1e12)
//                    + (C-1)*1e-12
// Single fused kernel, last-block-done finalize.
// Sync design (sm_103a-specific): NO __threadfence in the common path —
// gpu-scope fence emits CCTL.IVALL (full L1D flush) per block, which cost
// ~7us chip-wide in R4. Instead each block's counter increment is an
// atom.release.gpu (orders the preceding L2 bucket atomic, no L1 flush);
// only the single last block pays one acquire fence before reading buckets.

#define B_ROWS 16384
#define C_CLASSES 1000
#define D_DIM 512
#define WARPS_PER_BLOCK 8
#define THREADS (WARPS_PER_BLOCK * 32)
#define GRID_BLOCKS (B_ROWS / WARPS_PER_BLOCK)   // 2048
#define N_BUCKETS 32

__device__ double g_buckets[N_BUCKETS];          // zero-initialized at load
__device__ unsigned int g_done = 0;

__global__ __launch_bounds__(THREADS) void center_loss_fused(
    const float* __restrict__ x,
    const int* __restrict__ labels,
    const float* __restrict__ centers,
    float* __restrict__ out)
{
    __shared__ double block_sum;
    const int warp_in_block = threadIdx.x >> 5;
    const int lane = threadIdx.x & 31;
    const int row = blockIdx.x * WARPS_PER_BLOCK + warp_in_block;

    if (threadIdx.x == 0) block_sum = 0.0;
    __syncthreads();

    {
        int lbl = labels[row];
        lbl = (lbl < 0) ? 0 : ((lbl >= C_CLASSES) ? C_CLASSES - 1 : lbl);

        const float4* __restrict__ xr =
            reinterpret_cast<const float4*>(x + (size_t)row * D_DIM);
        const float4* __restrict__ cr =
            reinterpret_cast<const float4*>(centers + (size_t)lbl * D_DIM);

        // 512 floats / 32 lanes = 4 float4 per lane; loads front-batched.
        float4 xv[4], cv[4];
#pragma unroll
        for (int i = 0; i < 4; i++) xv[i] = xr[lane + 32 * i];
#pragma unroll
        for (int i = 0; i < 4; i++) cv[i] = cr[lane + 32 * i];

        float xs = 0.f, cs = 0.f, xc = 0.f;
#pragma unroll
        for (int i = 0; i < 4; i++) {
            xs = fmaf(xv[i].x, xv[i].x, xs);
            xs = fmaf(xv[i].y, xv[i].y, xs);
            xs = fmaf(xv[i].z, xv[i].z, xs);
            xs = fmaf(xv[i].w, xv[i].w, xs);
            cs = fmaf(cv[i].x, cv[i].x, cs);
            cs = fmaf(cv[i].y, cv[i].y, cs);
            cs = fmaf(cv[i].z, cv[i].z, cs);
            cs = fmaf(cv[i].w, cv[i].w, cs);
            xc = fmaf(xv[i].x, cv[i].x, xc);
            xc = fmaf(xv[i].y, cv[i].y, xc);
            xc = fmaf(xv[i].z, cv[i].z, xc);
            xc = fmaf(xv[i].w, cv[i].w, xc);
        }

#pragma unroll
        for (int o = 16; o > 0; o >>= 1) {
            xs += __shfl_xor_sync(0xFFFFFFFFu, xs, o);
            cs += __shfl_xor_sync(0xFFFFFFFFu, cs, o);
            xc += __shfl_xor_sync(0xFFFFFFFFu, xc, o);
        }

        if (lane == 0) {
            float d = xs + cs - 2.0f * xc;     // same formula as reference
            d = fminf(fmaxf(d, 1e-12f), 1e12f);
            atomicAdd(&block_sum, (double)d);
        }
    }
    __syncthreads();

    if (threadIdx.x == 0) {
        // bucket add (L2 atomic) — spread over 32 addresses to dodge the
        // same-address ATOMG serialization floor
        atomicAdd(&g_buckets[blockIdx.x & (N_BUCKETS - 1)], block_sum);

        // release-increment: orders the bucket add before the count bump,
        // WITHOUT the CCTL.IVALL an explicit gpu fence would emit
        unsigned int prev;
        asm volatile("atom.release.gpu.global.add.u32 %0, [%1], %2;"
                     : "=r"(prev) : "l"(&g_done), "r"(1u) : "memory");

        if (prev == GRID_BLOCKS - 1) {
            // only this ONE block pays an acquire fence (single CCTL)
            __threadfence();
            double total = 0.0;
#pragma unroll
            for (int i = 0; i < N_BUCKETS; i++) {
                // atomic read: L2-coherent, immune to stale L1
                total += atomicAdd(&g_buckets[i], 0.0);
            }
            double loss = total / (double)B_ROWS
                        + (double)(C_CLASSES - 1) * 1e-12;
            out[0] = (float)loss;
            // reset for next graph replay (kernel completion publishes these)
#pragma unroll
            for (int i = 0; i < N_BUCKETS; i++) g_buckets[i] = 0.0;
            g_done = 0u;
        }
    }
}

extern "C" void kernel_launch(void* const* d_in, const int* in_sizes, int n_in,
                              void* d_out, int out_size)
{
    const float* x = (const float*)d_in[0];
    const int* labels = (const int*)d_in[1];
    const float* centers = (const float*)d_in[2];
    float* out = (float*)d_out;

    center_loss_fused<<<GRID_BLOCKS, THREADS>>>(x, labels, centers, out);
}